// round 8
// baseline (speedup 1.0000x reference)
#include <cuda_runtime.h>
#include <math.h>

#define EPS_F 1.1920928955078125e-07f
#define RED_THREADS 128
#define MAX_C 64
#define SEGS 2

// scratch (allocation-free rule)
__device__ float g_partials[256 * MAX_C * SEGS * 2];  // [b][c][seg][{sum,sumsq}]
__device__ float g_stats[512];                        // [b][{scale,bias}]
__device__ int   g_arrived = 0;                       // last-block counter (self-resetting)

// ---------------------------------------------------------------------------
// Kernel 1: per-(batch,row,half) prefix sum & sumsq + fused stats fold.
// grid = (B, C, SEGS), 128 threads. Each block: <=1024 float4 (8/thread, MLP=8).
// Last block to arrive folds partials into scale/bias (deterministic order).
// ---------------------------------------------------------------------------
__global__ void reduce_kernel(const float* __restrict__ data,
                              const int* __restrict__ zero_pos,
                              int C, int L, int nblocks) {
    int b   = blockIdx.x;
    int c   = blockIdx.y;
    int seg = blockIdx.z;
    int zp  = zero_pos[b];
    int tid = threadIdx.x;

    const float*  row  = data + ((size_t)b * C + c) * L;
    const float4* row4 = (const float4*)row;

    int zp4    = zp >> 2;
    int zrem   = zp & 3;
    int seg_lo = seg * 1024;              // float4 index range of this half-row

    float s = 0.0f, sq = 0.0f;
    {
        float4 v[8];
        int    valid[8];
#pragma unroll
        for (int k = 0; k < 8; k++) {
            int idx  = seg_lo + tid + k * RED_THREADS;
            valid[k] = (idx < zp4);
            if (valid[k]) v[k] = row4[idx];       // up to 8 loads in flight
        }
        float s0 = 0.f, q0 = 0.f, s1 = 0.f, q1 = 0.f;
#pragma unroll
        for (int k = 0; k < 8; k += 2) {
            if (valid[k]) {
                s0 += v[k].x + v[k].y + v[k].z + v[k].w;
                q0 += v[k].x * v[k].x + v[k].y * v[k].y + v[k].z * v[k].z + v[k].w * v[k].w;
            }
            if (valid[k + 1]) {
                s1 += v[k+1].x + v[k+1].y + v[k+1].z + v[k+1].w;
                q1 += v[k+1].x * v[k+1].x + v[k+1].y * v[k+1].y + v[k+1].z * v[k+1].z + v[k+1].w * v[k+1].w;
            }
        }
        s = s0 + s1;
        sq = q0 + q1;
    }

    // scalar remainder (zp % 4) handled by the segment containing zp4
    if (zp4 >= seg_lo && zp4 < seg_lo + 1024 && tid < zrem) {
        float x = row[(zp4 << 2) + tid];
        s  += x;
        sq += x * x;
    }

    // block reduction (128 threads = 4 warps)
    __shared__ float sh_s[RED_THREADS];
    __shared__ float sh_q[RED_THREADS];
    sh_s[tid] = s;
    sh_q[tid] = sq;
    __syncthreads();
    if (tid < 64) { sh_s[tid] += sh_s[tid + 64]; sh_q[tid] += sh_q[tid + 64]; }
    __syncthreads();
    if (tid < 32) {
        float vs = sh_s[tid] + sh_s[tid + 32];
        float vq = sh_q[tid] + sh_q[tid + 32];
        for (int off = 16; off > 0; off >>= 1) {
            vs += __shfl_down_sync(0xFFFFFFFFu, vs, off);
            vq += __shfl_down_sync(0xFFFFFFFFu, vq, off);
        }
        if (tid == 0) {
            int slot = ((b * MAX_C + c) * SEGS + seg) * 2;
            g_partials[slot + 0] = vs;
            g_partials[slot + 1] = vq;
        }
    }

    // ---- last-block stats fold ----
    __shared__ int sh_last;
    __threadfence();
    __syncthreads();
    if (tid == 0) {
        int old = atomicAdd(&g_arrived, 1);
        sh_last = (old == nblocks - 1);
    }
    __syncthreads();
    if (sh_last) {
        if (tid < 64) {                   // one thread per batch (B <= 64)
            int bb = tid;
            float ts = 0.0f, tq = 0.0f;
            for (int j = 0; j < C * SEGS; j++) {
                int slot = (bb * MAX_C * SEGS + j) * 2;
                ts += g_partials[slot + 0];
                tq += g_partials[slot + 1];
            }
            float cnt   = (float)C * (float)zero_pos[bb];
            float mean  = ts / cnt;
            float var   = (tq - cnt * mean * mean) / (cnt - 1.0f);
            float scale = 1.0f / (sqrtf(var) + EPS_F);
            g_stats[2 * bb + 0] = scale;
            g_stats[2 * bb + 1] = -mean * scale;
        }
        __syncthreads();
        if (tid == 0) g_arrived = 0;      // reset for next graph replay
    }
}

// ---------------------------------------------------------------------------
// Kernel 2: normalize full tensor + emit tail (idxes, zero_pos cast to float).
// Plain loads on data (exploit L2 lines warmed by reduce); streaming stores.
// ---------------------------------------------------------------------------
__global__ void norm_tail_kernel(const float4* __restrict__ data4,
                                 const int4* __restrict__ idxes4,
                                 const int4* __restrict__ zp4,
                                 float4* __restrict__ out4,
                                 int n4, int nidx4, int total4,
                                 int cl4_shift) {
    int stride = gridDim.x * blockDim.x;
    for (int i = blockIdx.x * blockDim.x + threadIdx.x; i < total4; i += stride) {
        float4 o;
        if (i < n4) {
            int b = i >> cl4_shift;
            float scale = g_stats[2 * b + 0];
            float bias  = g_stats[2 * b + 1];
            float4 v = data4[i];
            o.x = fmaf(v.x, scale, bias);
            o.y = fmaf(v.y, scale, bias);
            o.z = fmaf(v.z, scale, bias);
            o.w = fmaf(v.w, scale, bias);
        } else {
            int j = i - n4;
            int4 t = (j < nidx4) ? __ldcs(idxes4 + j) : __ldcs(zp4 + (j - nidx4));
            o.x = (float)t.x;
            o.y = (float)t.y;
            o.z = (float)t.z;
            o.w = (float)t.w;
        }
        __stcs(out4 + i, o);
    }
}

extern "C" void kernel_launch(void* const* d_in, const int* in_sizes, int n_in,
                              void* d_out, int out_size) {
    const float* data     = (const float*)d_in[0];
    const int*   idxes    = (const int*)d_in[1];
    const int*   zero_pos = (const int*)d_in[2];
    float*       out      = (float*)d_out;

    int n_data = in_sizes[0];            // B*C*L = 33554432
    int n_idx  = in_sizes[1];            // B*L   = 524288
    int B      = in_sizes[2];            // 64
    int CL     = n_data / B;             // 524288
    int L      = n_idx / B;              // 8192
    int C      = CL / L;                 // 64

    // 1) reduce + fused stats: half-row blocks
    dim3 g1(B, C, SEGS);
    int nblocks = B * C * SEGS;
    reduce_kernel<<<g1, RED_THREADS>>>(data, zero_pos, C, L, nblocks);

    // 2) fused normalize + tail
    int n4  = n_data / 4;
    int cl4 = CL / 4;
    int cl4_shift = 0;
    while ((1 << cl4_shift) < cl4) cl4_shift++;   // CL/4 power of two

    int total  = (out_size > n_data) ? out_size : n_data;
    int total4 = total / 4;
    int nidx4  = n_idx / 4;

    int nb = (total4 + 4 * 256 - 1) / (4 * 256);  // ~4 float4 per thread
    norm_tail_kernel<<<nb, 256>>>((const float4*)data,
                                  (const int4*)idxes,
                                  (const int4*)zero_pos,
                                  (float4*)out,
                                  n4, nidx4, total4, cl4_shift);
}

// round 9
// speedup vs baseline: 1.0620x; 1.0620x over previous
#include <cuda_runtime.h>
#include <math.h>

#define EPS_F 1.1920928955078125e-07f
#define RED_THREADS 256
#define MAX_C 64

// scratch (allocation-free rule): partial sums + final stats
__device__ float g_partials[256 * MAX_C * 2];  // [b][c][{sum,sumsq}]
__device__ float g_stats[512];                 // [b][{scale,bias}]

// ---------------------------------------------------------------------------
// Kernel 1: per-(batch,row) prefix sum & sumsq. grid = (B, C), one row/block.
// zp4 <= 2048 = 8 * 256: fully-unrolled predicated 8-load body, MLP=8.
// (R6 shape — measured 18.6us; R8's fused-fold variant regressed, reverted.)
// ---------------------------------------------------------------------------
__global__ void reduce_kernel(const float* __restrict__ data,
                              const int* __restrict__ zero_pos,
                              int C, int L) {
    int b  = blockIdx.x;
    int c  = blockIdx.y;
    int zp = zero_pos[b];

    const float* row = data + ((size_t)b * C + c) * L;
    int zp4  = zp >> 2;
    int zrem = zp & 3;
    int tid  = threadIdx.x;

    const float4* row4 = (const float4*)row;

    float4 v[8];
    int    valid[8];
#pragma unroll
    for (int k = 0; k < 8; k++) {
        int idx  = tid + k * RED_THREADS;
        valid[k] = (idx < zp4);
        if (valid[k]) v[k] = row4[idx];           // 8 independent loads in flight
    }

    float s0 = 0.f, q0 = 0.f, s1 = 0.f, q1 = 0.f;
#pragma unroll
    for (int k = 0; k < 8; k += 2) {
        if (valid[k]) {
            s0 += v[k].x + v[k].y + v[k].z + v[k].w;
            q0 += v[k].x * v[k].x + v[k].y * v[k].y + v[k].z * v[k].z + v[k].w * v[k].w;
        }
        if (valid[k + 1]) {
            s1 += v[k+1].x + v[k+1].y + v[k+1].z + v[k+1].w;
            q1 += v[k+1].x * v[k+1].x + v[k+1].y * v[k+1].y + v[k+1].z * v[k+1].z + v[k+1].w * v[k+1].w;
        }
    }
    float s = s0 + s1, sq = q0 + q1;

    if (tid < zrem) {
        float x = row[(zp4 << 2) + tid];
        s  += x;
        sq += x * x;
    }

    // block reduction
    __shared__ float sh_s[RED_THREADS];
    __shared__ float sh_q[RED_THREADS];
    sh_s[tid] = s;
    sh_q[tid] = sq;
    __syncthreads();
    for (int off = RED_THREADS / 2; off >= 32; off >>= 1) {
        if (tid < off) {
            sh_s[tid] += sh_s[tid + off];
            sh_q[tid] += sh_q[tid + off];
        }
        __syncthreads();
    }
    if (tid < 32) {
        float vs = sh_s[tid];
        float vq = sh_q[tid];
        for (int off = 16; off > 0; off >>= 1) {
            vs += __shfl_down_sync(0xFFFFFFFFu, vs, off);
            vq += __shfl_down_sync(0xFFFFFFFFu, vq, off);
        }
        if (tid == 0) {
            int slot = (b * MAX_C + c) * 2;
            g_partials[slot + 0] = vs;
            g_partials[slot + 1] = vq;
        }
    }
}

// ---------------------------------------------------------------------------
// Kernel 2: fold partials -> scale = 1/(std+eps), bias = -mean*scale.
// ---------------------------------------------------------------------------
__global__ void stats_kernel(const int* __restrict__ zero_pos, int C) {
    int b = threadIdx.x;
    float s = 0.0f, sq = 0.0f;
    for (int j = 0; j < C; j++) {
        int slot = (b * MAX_C + j) * 2;
        s  += g_partials[slot + 0];
        sq += g_partials[slot + 1];
    }
    float cnt   = (float)C * (float)zero_pos[b];
    float mean  = s / cnt;
    float var   = (sq - cnt * mean * mean) / (cnt - 1.0f);
    float scale = 1.0f / (sqrtf(var) + EPS_F);
    g_stats[2 * b + 0] = scale;
    g_stats[2 * b + 1] = -mean * scale;
}

// ---------------------------------------------------------------------------
// Kernel 3: normalize. Exact tiling: n4 = nb_data*256*4, no loop, no bounds.
// Block's 1024 float4 all in one batch -> uniform scale/bias load.
// 4 independent float4 loads per thread (MLP=4), streaming stores.
// ---------------------------------------------------------------------------
__global__ void norm_kernel(const float4* __restrict__ data4,
                            float4* __restrict__ out4,
                            int cl4_shift) {
    int base = blockIdx.x * (256 * 4);
    int b    = base >> cl4_shift;           // uniform across block
    float scale = g_stats[2 * b + 0];
    float bias  = g_stats[2 * b + 1];

    int i0 = base + threadIdx.x;
    float4 v0 = data4[i0];
    float4 v1 = data4[i0 + 256];
    float4 v2 = data4[i0 + 512];
    float4 v3 = data4[i0 + 768];

    float4 o0, o1, o2, o3;
    o0.x = fmaf(v0.x, scale, bias); o0.y = fmaf(v0.y, scale, bias);
    o0.z = fmaf(v0.z, scale, bias); o0.w = fmaf(v0.w, scale, bias);
    o1.x = fmaf(v1.x, scale, bias); o1.y = fmaf(v1.y, scale, bias);
    o1.z = fmaf(v1.z, scale, bias); o1.w = fmaf(v1.w, scale, bias);
    o2.x = fmaf(v2.x, scale, bias); o2.y = fmaf(v2.y, scale, bias);
    o2.z = fmaf(v2.z, scale, bias); o2.w = fmaf(v2.w, scale, bias);
    o3.x = fmaf(v3.x, scale, bias); o3.y = fmaf(v3.y, scale, bias);
    o3.z = fmaf(v3.z, scale, bias); o3.w = fmaf(v3.w, scale, bias);

    __stcs(out4 + i0,       o0);
    __stcs(out4 + i0 + 256, o1);
    __stcs(out4 + i0 + 512, o2);
    __stcs(out4 + i0 + 768, o3);
}

// ---------------------------------------------------------------------------
// Kernel 4: tail — idxes and zero_pos cast to float, int4/float4 vectorized.
// ---------------------------------------------------------------------------
__global__ void tail_kernel(const int4* __restrict__ idxes4,
                            const int4* __restrict__ zp4,
                            float4* __restrict__ out_tail4,
                            int nidx4, int ntail4) {
    int i = blockIdx.x * blockDim.x + threadIdx.x;
    if (i < ntail4) {
        int4 t = (i < nidx4) ? __ldcs(idxes4 + i) : __ldcs(zp4 + (i - nidx4));
        float4 o;
        o.x = (float)t.x; o.y = (float)t.y; o.z = (float)t.z; o.w = (float)t.w;
        __stcs(out_tail4 + i, o);
    }
}

extern "C" void kernel_launch(void* const* d_in, const int* in_sizes, int n_in,
                              void* d_out, int out_size) {
    const float* data     = (const float*)d_in[0];
    const int*   idxes    = (const int*)d_in[1];
    const int*   zero_pos = (const int*)d_in[2];
    float*       out      = (float*)d_out;

    int n_data = in_sizes[0];            // B*C*L = 33554432
    int n_idx  = in_sizes[1];            // B*L   = 524288
    int B      = in_sizes[2];            // 64
    int CL     = n_data / B;             // 524288
    int L      = n_idx / B;              // 8192
    int C      = CL / L;                 // 64

    // 1) partial reductions over prefixes: one row per block, MLP=8
    dim3 g1(B, C);
    reduce_kernel<<<g1, RED_THREADS>>>(data, zero_pos, C, L);

    // 2) stats
    stats_kernel<<<1, B>>>(zero_pos, C);

    // 3) normalize data region (exact tiling: n_data divisible by 1024*4)
    int n4  = n_data / 4;
    int cl4 = CL / 4;
    int cl4_shift = 0;
    while ((1 << cl4_shift) < cl4) cl4_shift++;   // CL/4 power of two

    int nb_data = n4 / (256 * 4);                 // exact (8192)
    norm_kernel<<<nb_data, 256>>>((const float4*)data, (float4*)out, cl4_shift);

    // 4) tail (idxes + zero_pos)
    long long extra = (long long)out_size - (long long)n_data;
    if (extra > 0) {
        int ntail4 = (int)(extra / 4);            // n_idx and B divisible by 4
        int nidx4  = n_idx / 4;
        if (ntail4 > nidx4 + B / 4) ntail4 = nidx4 + B / 4;
        int tb = (ntail4 + 255) / 256;
        tail_kernel<<<tb, 256>>>((const int4*)idxes, (const int4*)zero_pos,
                                 (float4*)(out + n_data), nidx4, ntail4);
    }
}

// round 10
// speedup vs baseline: 1.1723x; 1.1038x over previous
#include <cuda_runtime.h>
#include <math.h>

#define EPS_F 1.1920928955078125e-07f
#define RED_THREADS 256
#define MAX_C 64

// scratch (allocation-free rule): partial sums + final stats
__device__ float g_partials[256 * MAX_C * 2];  // [b][slot][{sum,sumsq}]
__device__ float g_stats[512];                 // [b][{scale,bias}]

// ---------------------------------------------------------------------------
// Kernel 1: prefix sum & sumsq, TWO rows per block (same batch -> same zp,
// shared predicates, one partial slot). grid = (B, C/2), 256 threads.
// 16 interleaved float4 loads per thread -> MLP 16, half the block overhead.
// ---------------------------------------------------------------------------
__global__ void reduce_kernel(const float* __restrict__ data,
                              const int* __restrict__ zero_pos,
                              int C, int L) {
    int b  = blockIdx.x;
    int c0 = blockIdx.y * 2;
    int zp = zero_pos[b];

    const float* row0 = data + ((size_t)b * C + c0) * L;
    const float* row1 = row0 + L;
    int zp4  = zp >> 2;
    int zrem = zp & 3;
    int tid  = threadIdx.x;

    const float4* r40 = (const float4*)row0;
    const float4* r41 = (const float4*)row1;

    float4 va[8], vb[8];
    int    valid[8];
#pragma unroll
    for (int k = 0; k < 8; k++) {
        int idx  = tid + k * RED_THREADS;
        valid[k] = (idx < zp4);
        if (valid[k]) { va[k] = r40[idx]; vb[k] = r41[idx]; }  // 16 loads in flight
    }

    float s0 = 0.f, q0 = 0.f, s1 = 0.f, q1 = 0.f;
#pragma unroll
    for (int k = 0; k < 8; k++) {
        if (valid[k]) {
            s0 += va[k].x + va[k].y + va[k].z + va[k].w;
            q0 += va[k].x * va[k].x + va[k].y * va[k].y + va[k].z * va[k].z + va[k].w * va[k].w;
            s1 += vb[k].x + vb[k].y + vb[k].z + vb[k].w;
            q1 += vb[k].x * vb[k].x + vb[k].y * vb[k].y + vb[k].z * vb[k].z + vb[k].w * vb[k].w;
        }
    }
    float s = s0 + s1, sq = q0 + q1;

    if (tid < zrem) {
        float x = row0[(zp4 << 2) + tid];
        float y = row1[(zp4 << 2) + tid];
        s  += x + y;
        sq += x * x + y * y;
    }

    // block reduction
    __shared__ float sh_s[RED_THREADS];
    __shared__ float sh_q[RED_THREADS];
    sh_s[tid] = s;
    sh_q[tid] = sq;
    __syncthreads();
    for (int off = RED_THREADS / 2; off >= 32; off >>= 1) {
        if (tid < off) {
            sh_s[tid] += sh_s[tid + off];
            sh_q[tid] += sh_q[tid + off];
        }
        __syncthreads();
    }
    if (tid < 32) {
        float vs = sh_s[tid];
        float vq = sh_q[tid];
        for (int off = 16; off > 0; off >>= 1) {
            vs += __shfl_down_sync(0xFFFFFFFFu, vs, off);
            vq += __shfl_down_sync(0xFFFFFFFFu, vq, off);
        }
        if (tid == 0) {
            int slot = (b * MAX_C + blockIdx.y) * 2;
            g_partials[slot + 0] = vs;
            g_partials[slot + 1] = vq;
        }
    }
}

// ---------------------------------------------------------------------------
// Kernel 2: fold partials -> scale = 1/(std+eps), bias = -mean*scale.
// ---------------------------------------------------------------------------
__global__ void stats_kernel(const int* __restrict__ zero_pos, int C, int nslots) {
    int b = threadIdx.x;
    float s = 0.0f, sq = 0.0f;
    for (int j = 0; j < nslots; j++) {
        int slot = (b * MAX_C + j) * 2;
        s  += g_partials[slot + 0];
        sq += g_partials[slot + 1];
    }
    float cnt   = (float)C * (float)zero_pos[b];
    float mean  = s / cnt;
    float var   = (sq - cnt * mean * mean) / (cnt - 1.0f);
    float scale = 1.0f / (sqrtf(var) + EPS_F);
    g_stats[2 * b + 0] = scale;
    g_stats[2 * b + 1] = -mean * scale;
}

// ---------------------------------------------------------------------------
// Kernel 3: fused normalize + tail in ONE launch.
// Blocks [0, nb_data): exact tiling, no bounds, uniform scale/bias per block,
//   4 independent float4 loads, streaming stores.
// Blocks [nb_data, ...): convert idxes/zero_pos (int4 -> float4) with bounds.
// ---------------------------------------------------------------------------
__global__ void norm_tail_kernel(const float4* __restrict__ data4,
                                 const int4* __restrict__ idxes4,
                                 const int4* __restrict__ zp4,
                                 float4* __restrict__ out4,
                                 int nb_data, int cl4_shift,
                                 int n4, int nidx4, int ntail4) {
    if (blockIdx.x < nb_data) {
        int base = blockIdx.x * (256 * 4);
        int b    = base >> cl4_shift;           // uniform across block
        float scale = g_stats[2 * b + 0];
        float bias  = g_stats[2 * b + 1];

        int i0 = base + threadIdx.x;
        float4 v0 = data4[i0];
        float4 v1 = data4[i0 + 256];
        float4 v2 = data4[i0 + 512];
        float4 v3 = data4[i0 + 768];

        float4 o0, o1, o2, o3;
        o0.x = fmaf(v0.x, scale, bias); o0.y = fmaf(v0.y, scale, bias);
        o0.z = fmaf(v0.z, scale, bias); o0.w = fmaf(v0.w, scale, bias);
        o1.x = fmaf(v1.x, scale, bias); o1.y = fmaf(v1.y, scale, bias);
        o1.z = fmaf(v1.z, scale, bias); o1.w = fmaf(v1.w, scale, bias);
        o2.x = fmaf(v2.x, scale, bias); o2.y = fmaf(v2.y, scale, bias);
        o2.z = fmaf(v2.z, scale, bias); o2.w = fmaf(v2.w, scale, bias);
        o3.x = fmaf(v3.x, scale, bias); o3.y = fmaf(v3.y, scale, bias);
        o3.z = fmaf(v3.z, scale, bias); o3.w = fmaf(v3.w, scale, bias);

        __stcs(out4 + i0,       o0);
        __stcs(out4 + i0 + 256, o1);
        __stcs(out4 + i0 + 512, o2);
        __stcs(out4 + i0 + 768, o3);
    } else {
        int i = (blockIdx.x - nb_data) * 256 + threadIdx.x;
        if (i < ntail4) {
            int4 t = (i < nidx4) ? __ldcs(idxes4 + i) : __ldcs(zp4 + (i - nidx4));
            float4 o;
            o.x = (float)t.x; o.y = (float)t.y; o.z = (float)t.z; o.w = (float)t.w;
            __stcs(out4 + n4 + i, o);
        }
    }
}

extern "C" void kernel_launch(void* const* d_in, const int* in_sizes, int n_in,
                              void* d_out, int out_size) {
    const float* data     = (const float*)d_in[0];
    const int*   idxes    = (const int*)d_in[1];
    const int*   zero_pos = (const int*)d_in[2];
    float*       out      = (float*)d_out;

    int n_data = in_sizes[0];            // B*C*L = 33554432
    int n_idx  = in_sizes[1];            // B*L   = 524288
    int B      = in_sizes[2];            // 64
    int CL     = n_data / B;             // 524288
    int L      = n_idx / B;              // 8192
    int C      = CL / L;                 // 64

    // 1) reduce: two rows per block, MLP 16
    dim3 g1(B, C / 2);
    reduce_kernel<<<g1, RED_THREADS>>>(data, zero_pos, C, L);

    // 2) stats
    stats_kernel<<<1, B>>>(zero_pos, C, C / 2);

    // 3) fused normalize + tail
    int n4  = n_data / 4;
    int cl4 = CL / 4;
    int cl4_shift = 0;
    while ((1 << cl4_shift) < cl4) cl4_shift++;   // CL/4 power of two

    int nb_data = n4 / (256 * 4);                 // exact tiling (8192 blocks)

    long long extra = (long long)out_size - (long long)n_data;
    int ntail4 = 0, nidx4 = n_idx / 4;
    if (extra > 0) {
        ntail4 = (int)(extra / 4);
        if (ntail4 > nidx4 + B / 4) ntail4 = nidx4 + B / 4;
    }
    int nb_tail = (ntail4 + 255) / 256;

    norm_tail_kernel<<<nb_data + nb_tail, 256>>>((const float4*)data,
                                                 (const int4*)idxes,
                                                 (const int4*)zero_pos,
                                                 (float4*)out,
                                                 nb_data, cl4_shift,
                                                 n4, nidx4, ntail4);
}